// round 8
// baseline (speedup 1.0000x reference)
#include <cuda_runtime.h>
#include <cuda_bf16.h>

#define CLASS_NUM 512
#define B_ROWS    1024
#define E_ROWS    50000
#define OUT_ELEMS (B_ROWS * E_ROWS)   // 51,200,000
#define E4TOT     (E_ROWS / 4)        // 12,500 float4 per output row

// Fused-kernel tiling: each block owns E_TILE consecutive e values.
#define E_TILE   64
#define E4_TILE  (E_TILE / 4)         // 16 float4
#define NBLOCKS  ((E_ROWS + E_TILE - 1) / E_TILE)  // 782

// Scratch (no device allocation allowed).
__device__ float g_hr[B_ROWS];        // hr_part[b] + bias (bias folded)

// ---------------------------------------------------------------------------
// Kernel A (tiny, ~2us): g_hr[b] = dot(hr[b], W1) + bias.  Warp-per-row.
// ---------------------------------------------------------------------------
__global__ void __launch_bounds__(256)
hr_kernel(const float* __restrict__ hr,
          const float* __restrict__ W,
          const float* __restrict__ bias)
{
    const int row  = (blockIdx.x * blockDim.x + threadIdx.x) >> 5;
    const int lane = threadIdx.x & 31;
    if (row >= B_ROWS) return;

    const float4* s4 = reinterpret_cast<const float4*>(hr + (size_t)row * CLASS_NUM);
    const float4* w4 = reinterpret_cast<const float4*>(W);

    float sum = 0.0f;
#pragma unroll
    for (int k = 0; k < 4; k++) {
        int j = lane + k * 32;
        float4 a = __ldg(&s4[j]);
        float4 c = __ldg(&w4[j]);
        sum = fmaf(a.x, c.x, sum);
        sum = fmaf(a.y, c.y, sum);
        sum = fmaf(a.z, c.z, sum);
        sum = fmaf(a.w, c.w, sum);
    }
#pragma unroll
    for (int off = 16; off > 0; off >>= 1)
        sum += __shfl_xor_sync(0xFFFFFFFFu, sum, off);

    if (lane == 0)
        g_hr[row] = sum + __ldg(bias);
}

// ---------------------------------------------------------------------------
// Kernel B (fused): per block of 256 threads, e-tile of 64:
//   phase a: 8 warps x 8 rows -> 64 tail dots into smem   (128 KB DRAM read)
//   phase b: write out[b][e-tile] for all 1024 b          (256 KB DRAM write)
// Reads and writes from different blocks interleave chip-wide -> mixed
// DRAM stream instead of a serialized read phase then write phase.
// ---------------------------------------------------------------------------
__global__ void __launch_bounds__(256)
fused_kernel(const float* __restrict__ tail,
             const float* __restrict__ W,
             float4* __restrict__ out)
{
    __shared__ float s_tail[E_TILE];

    const int e0   = blockIdx.x * E_TILE;
    const int wid  = threadIdx.x >> 5;
    const int lane = threadIdx.x & 31;

    // W2 in registers (L1-hit loads, 4 float4 per lane covers 512 floats/warp)
    const float4* w4 = reinterpret_cast<const float4*>(W + CLASS_NUM);
    const float4 c0 = __ldg(&w4[lane]);
    const float4 c1 = __ldg(&w4[lane + 32]);
    const float4 c2 = __ldg(&w4[lane + 64]);
    const float4 c3 = __ldg(&w4[lane + 96]);

    // ---- phase a: each warp computes 8 consecutive tail dots ----
#pragma unroll
    for (int r = 0; r < 8; r++) {
        const int el = wid * 8 + r;            // 0..63 within tile
        const int e  = e0 + el;
        if (e < E_ROWS) {
            const float4* s4 = reinterpret_cast<const float4*>(tail + (size_t)e * CLASS_NUM);
            float4 a0 = __ldcs(&s4[lane]);
            float4 a1 = __ldcs(&s4[lane + 32]);
            float4 a2 = __ldcs(&s4[lane + 64]);
            float4 a3 = __ldcs(&s4[lane + 96]);
            float sum = 0.0f;
            sum = fmaf(a0.x, c0.x, sum); sum = fmaf(a0.y, c0.y, sum);
            sum = fmaf(a0.z, c0.z, sum); sum = fmaf(a0.w, c0.w, sum);
            sum = fmaf(a1.x, c1.x, sum); sum = fmaf(a1.y, c1.y, sum);
            sum = fmaf(a1.z, c1.z, sum); sum = fmaf(a1.w, c1.w, sum);
            sum = fmaf(a2.x, c2.x, sum); sum = fmaf(a2.y, c2.y, sum);
            sum = fmaf(a2.z, c2.z, sum); sum = fmaf(a2.w, c2.w, sum);
            sum = fmaf(a3.x, c3.x, sum); sum = fmaf(a3.y, c3.y, sum);
            sum = fmaf(a3.z, c3.z, sum); sum = fmaf(a3.w, c3.w, sum);
#pragma unroll
            for (int off = 16; off > 0; off >>= 1)
                sum += __shfl_xor_sync(0xFFFFFFFFu, sum, off);
            if (lane == 0)
                s_tail[el] = sum;
        }
    }
    __syncthreads();

    // ---- phase b: stream the 1024-row x 64-col slab ----
    // thread -> (e4 within tile, starting row); 16 threads cover 256B/row.
    const int e4l  = threadIdx.x & 15;         // 0..15
    const int brow = threadIdx.x >> 4;         // 0..15
    const int e4g  = blockIdx.x * E4_TILE + e4l;
    if (e4g >= E4TOT) return;                  // partial last tile

    const float4 t = *reinterpret_cast<const float4*>(&s_tail[e4l * 4]);

    float4* dst = out + (size_t)brow * E4TOT + e4g;
#pragma unroll 4
    for (int b = brow; b < B_ROWS; b += 16) {
        const float h = __ldg(&g_hr[b]);       // L1-resident broadcast
        float4 v;
        v.x = h + t.x;
        v.y = h + t.y;
        v.z = h + t.z;
        v.w = h + t.w;
        __stcs(dst, v);                        // evict-first streaming store
        dst += 16 * E4TOT;
    }
}

// Zero any trailing elements beyond the scores matrix.
__global__ void zero_tail_kernel(float* __restrict__ out, int start, int total)
{
    int i = start + blockIdx.x * blockDim.x + threadIdx.x;
    if (i < total) out[i] = 0.0f;
}

extern "C" void kernel_launch(void* const* d_in, const int* in_sizes, int n_in,
                              void* d_out, int out_size)
{
    const float* hr   = (const float*)d_in[0];  // [1024, 512]
    const float* tail = (const float*)d_in[1];  // [50000, 512]
    const float* W    = (const float*)d_in[2];  // [1, 1024]
    const float* bias = (const float*)d_in[3];  // [1]
    float* out = (float*)d_out;

    // Kernel A: g_hr (1024 rows, 8 warps/block).
    hr_kernel<<<(B_ROWS * 32 + 255) / 256, 256>>>(hr, W, bias);

    // Kernel B: fused tail-dot + outer-sum stream.
    fused_kernel<<<NBLOCKS, 256>>>(tail, W, (float4*)out);

    // Zero any extra output elements (e.g. the appended scalar 0).
    if (out_size > OUT_ELEMS) {
        int extra = out_size - OUT_ELEMS;
        zero_tail_kernel<<<(extra + 255) / 256, 256>>>(out, OUT_ELEMS, out_size);
    }
}